// round 6
// baseline (speedup 1.0000x reference)
#include <cuda_runtime.h>
#include <cstdint>

// Problem constants
#define Bn 16
#define Tn 2048
#define Cn 128
#define Hn 128

// Scratch for projected Q, K, V (fp32). Static __device__ arrays: the sanctioned
// no-alloc workaround. 3 x 16 MB = 48 MB.
__device__ float g_Q[(size_t)Bn * Tn * Hn];
__device__ float g_K[(size_t)Bn * Tn * Hn];
__device__ float g_V[(size_t)Bn * Tn * Hn];

__device__ __forceinline__ uint32_t f2tf(float x) {
    uint32_t y;
    asm("cvt.rna.tf32.f32 %0, %1;" : "=r"(y) : "f"(x));
    return y;
}

__device__ __forceinline__ float fexp2(float x) {
    float y;
    asm("ex2.approx.f32 %0, %1;" : "=f"(y) : "f"(x));
    return y;
}

// D += A(16x8) * B(8x8), tf32 inputs, fp32 accumulate.
__device__ __forceinline__ void mma8(float* d,
                                     uint32_t a0, uint32_t a1, uint32_t a2, uint32_t a3,
                                     uint32_t b0, uint32_t b1) {
    asm volatile(
        "mma.sync.aligned.m16n8k8.row.col.f32.tf32.tf32.f32 "
        "{%0,%1,%2,%3},{%4,%5,%6,%7},{%8,%9},{%0,%1,%2,%3};"
        : "+f"(d[0]), "+f"(d[1]), "+f"(d[2]), "+f"(d[3])
        : "r"(a0), "r"(a1), "r"(a2), "r"(a3), "r"(b0), "r"(b1));
}

__device__ __forceinline__ void st4tf(float* d, float4 v, float s) {
    d[0] = __uint_as_float(f2tf(v.x * s));
    d[1] = __uint_as_float(f2tf(v.y * s));
    d[2] = __uint_as_float(f2tf(v.z * s));
    d[3] = __uint_as_float(f2tf(v.w * s));
}

// ============================================================================
// Projection: out[m, n] = sum_c x[m, c] * W[n, c]
// M = B*T = 32768, K = 128, three Ws of N = 128 each.
// Block: 256 threads (8 warps), tile BM=128 x BN=64.
// grid.x = 256 m-tiles; grid.y = 6 (which W x which half of its 128 cols).
// ============================================================================
#define PROJ_SMEM ((128 * 132 + 64 * 132) * 4)

__global__ __launch_bounds__(256, 1) void proj_kernel(
    const float* __restrict__ x,
    const float* __restrict__ Wq,
    const float* __restrict__ Wk,
    const float* __restrict__ Wv) {
    extern __shared__ float sm[];
    float* sx = sm;               // [128][132] tf32
    float* sw = sm + 128 * 132;   // [64][132]  tf32

    const int tid = threadIdx.x;
    const int mt = blockIdx.x;
    const int wsel = blockIdx.y >> 1;
    const int nhalf = blockIdx.y & 1;
    const float* W = (wsel == 0) ? Wq : (wsel == 1 ? Wk : Wv);
    float* out = (wsel == 0) ? g_Q : (wsel == 1 ? g_K : g_V);

    // Load x tile [128,128] (float4, tf32-convert)
    const float* xg = x + (size_t)mt * 128 * Cn;
    for (int i = tid; i < 128 * 32; i += 256) {
        int r = i >> 5, c = (i & 31) << 2;
        float4 v = *(const float4*)(xg + r * Cn + c);
        st4tf(sx + r * 132 + c, v, 1.0f);
    }
    // Load W tile [64,128]
    const float* wg = W + (size_t)nhalf * 64 * Cn;
    for (int i = tid; i < 64 * 32; i += 256) {
        int r = i >> 5, c = (i & 31) << 2;
        float4 v = *(const float4*)(wg + r * Cn + c);
        st4tf(sw + r * 132 + c, v, 1.0f);
    }
    __syncthreads();

    const int wid = tid >> 5, lane = tid & 31;
    const int gr = lane >> 2, gc = lane & 3;
    const int m0 = wid * 16;

    float acc[8][4];
#pragma unroll
    for (int i = 0; i < 8; i++) { acc[i][0] = acc[i][1] = acc[i][2] = acc[i][3] = 0.f; }

#pragma unroll
    for (int k0 = 0; k0 < 128; k0 += 8) {
        uint32_t a0 = __float_as_uint(sx[(m0 + gr) * 132 + k0 + gc]);
        uint32_t a1 = __float_as_uint(sx[(m0 + gr + 8) * 132 + k0 + gc]);
        uint32_t a2 = __float_as_uint(sx[(m0 + gr) * 132 + k0 + gc + 4]);
        uint32_t a3 = __float_as_uint(sx[(m0 + gr + 8) * 132 + k0 + gc + 4]);
#pragma unroll
        for (int nt = 0; nt < 8; nt++) {
            uint32_t b0 = __float_as_uint(sw[(nt * 8 + gr) * 132 + k0 + gc]);
            uint32_t b1 = __float_as_uint(sw[(nt * 8 + gr) * 132 + k0 + gc + 4]);
            mma8(acc[nt], a0, a1, a2, a3, b0, b1);
        }
    }

    const int rbase = mt * 128 + m0;
    const int cbase = nhalf * 64;
#pragma unroll
    for (int nt = 0; nt < 8; nt++) {
        int col = cbase + nt * 8 + 2 * gc;
        *(float2*)(out + ((size_t)(rbase + gr)) * Hn + col) =
            make_float2(acc[nt][0], acc[nt][1]);
        *(float2*)(out + ((size_t)(rbase + gr + 8)) * Hn + col) =
            make_float2(acc[nt][2], acc[nt][3]);
    }
}

// ============================================================================
// Flash attention. Block = (q-tile of 128 rows, batch). 256 threads, 8 warps,
// each warp owns 16 query rows. Iterate key tiles of 64, online softmax.
// smem pads chosen so frag-load bank index == lane id (conflict-free):
//   Q,K stride 132; V stride 136; per-warp P stride 68.
// ============================================================================
#define ATTN_SMEM ((128 * 132 + 64 * 132 + 64 * 136 + 8 * 16 * 68) * 4)

__global__ __launch_bounds__(256, 1) void attn_kernel(float* __restrict__ out) {
    extern __shared__ float sm[];
    float* sQ = sm;                       // [128][132]
    float* sK = sQ + 128 * 132;           // [64][132]
    float* sV = sK + 64 * 132;            // [64][136]
    float* sP = sV + 64 * 136;            // [8][16][68] per-warp

    const int tid = threadIdx.x;
    const int wid = tid >> 5, lane = tid & 31;
    const int gr = lane >> 2, gc = lane & 3;
    const int qi = 15 - (int)blockIdx.x;  // heavy tiles first
    const int b = blockIdx.y;

    const float* Qg = g_Q + ((size_t)b * Tn + (size_t)qi * 128) * Hn;
    const float* Kg = g_K + (size_t)b * Tn * Hn;
    const float* Vg = g_V + (size_t)b * Tn * Hn;
    const float SC = 0.08838834764831845f;         // C^-0.5, folded into Q
    const float L2E = 1.4426950408889634f;

    // Load Q tile once (scaled, tf32)
    for (int i = tid; i < 128 * 32; i += 256) {
        int r = i >> 5, c = (i & 31) << 2;
        float4 v = *(const float4*)(Qg + r * Hn + c);
        st4tf(sQ + r * 132 + c, v, SC);
    }

    float o[16][4];
#pragma unroll
    for (int i = 0; i < 16; i++) { o[i][0] = o[i][1] = o[i][2] = o[i][3] = 0.f; }
    float mrow[2] = {-1e30f, -1e30f};
    float lrow[2] = {0.f, 0.f};
    const int m0 = wid * 16;
    const int nkt = 2 * qi + 2;

    for (int kj = 0; kj < nkt; kj++) {
        __syncthreads();  // protects sK/sV (and per-warp sP) from previous iter
        for (int i = tid; i < 64 * 32; i += 256) {
            int r = i >> 5, c = (i & 31) << 2;
            float4 kv = *(const float4*)(Kg + ((size_t)kj * 64 + r) * Hn + c);
            st4tf(sK + r * 132 + c, kv, 1.0f);
            float4 vv = *(const float4*)(Vg + ((size_t)kj * 64 + r) * Hn + c);
            st4tf(sV + r * 136 + c, vv, 1.0f);
        }
        __syncthreads();

        // S = Q * K^T  (warp: 16 x 64)
        float s[8][4];
#pragma unroll
        for (int i = 0; i < 8; i++) { s[i][0] = s[i][1] = s[i][2] = s[i][3] = 0.f; }
#pragma unroll
        for (int k0 = 0; k0 < 128; k0 += 8) {
            uint32_t a0 = __float_as_uint(sQ[(m0 + gr) * 132 + k0 + gc]);
            uint32_t a1 = __float_as_uint(sQ[(m0 + gr + 8) * 132 + k0 + gc]);
            uint32_t a2 = __float_as_uint(sQ[(m0 + gr) * 132 + k0 + gc + 4]);
            uint32_t a3 = __float_as_uint(sQ[(m0 + gr + 8) * 132 + k0 + gc + 4]);
#pragma unroll
            for (int nt = 0; nt < 8; nt++) {
                uint32_t b0 = __float_as_uint(sK[(nt * 8 + gr) * 132 + k0 + gc]);
                uint32_t b1 = __float_as_uint(sK[(nt * 8 + gr) * 132 + k0 + gc + 4]);
                mma8(s[nt], a0, a1, a2, a3, b0, b1);
            }
        }

        // Causal mask: only the two tiles touching the diagonal need it
        if (kj >= 2 * qi) {
            const int q0 = qi * 128 + m0 + gr;
#pragma unroll
            for (int nt = 0; nt < 8; nt++) {
                int cg = kj * 64 + nt * 8 + 2 * gc;
                if (cg > q0)         s[nt][0] = -1e30f;
                if (cg + 1 > q0)     s[nt][1] = -1e30f;
                if (cg > q0 + 8)     s[nt][2] = -1e30f;
                if (cg + 1 > q0 + 8) s[nt][3] = -1e30f;
            }
        }

        // Online softmax (rows r=gr -> h=0 regs [0..1]; r=gr+8 -> h=1 regs [2..3])
#pragma unroll
        for (int h = 0; h < 2; h++) {
            float rm = -1e30f;
#pragma unroll
            for (int nt = 0; nt < 8; nt++)
                rm = fmaxf(rm, fmaxf(s[nt][2 * h], s[nt][2 * h + 1]));
            rm = fmaxf(rm, __shfl_xor_sync(0xffffffffu, rm, 1));
            rm = fmaxf(rm, __shfl_xor_sync(0xffffffffu, rm, 2));
            float mn = fmaxf(mrow[h], rm);
            float alpha = fexp2((mrow[h] - mn) * L2E);
            mrow[h] = mn;
            float rs = 0.f;
#pragma unroll
            for (int nt = 0; nt < 8; nt++) {
                float p0 = fexp2((s[nt][2 * h] - mn) * L2E);
                float p1 = fexp2((s[nt][2 * h + 1] - mn) * L2E);
                s[nt][2 * h] = p0;
                s[nt][2 * h + 1] = p1;
                rs += p0 + p1;
            }
            rs += __shfl_xor_sync(0xffffffffu, rs, 1);
            rs += __shfl_xor_sync(0xffffffffu, rs, 2);
            lrow[h] = lrow[h] * alpha + rs;
#pragma unroll
            for (int ht = 0; ht < 16; ht++) {
                o[ht][2 * h] *= alpha;
                o[ht][2 * h + 1] *= alpha;
            }
        }

        // C-frag -> A-frag relayout of P through per-warp smem (tf32)
        float* pw = sP + wid * 16 * 68;
#pragma unroll
        for (int nt = 0; nt < 8; nt++) {
            int c = nt * 8 + 2 * gc;
            pw[gr * 68 + c]           = __uint_as_float(f2tf(s[nt][0]));
            pw[gr * 68 + c + 1]       = __uint_as_float(f2tf(s[nt][1]));
            pw[(gr + 8) * 68 + c]     = __uint_as_float(f2tf(s[nt][2]));
            pw[(gr + 8) * 68 + c + 1] = __uint_as_float(f2tf(s[nt][3]));
        }
        __syncwarp();

        // O += P * V  (warp: 16 x 128)
#pragma unroll
        for (int s0 = 0; s0 < 64; s0 += 8) {
            uint32_t a0 = __float_as_uint(pw[gr * 68 + s0 + gc]);
            uint32_t a1 = __float_as_uint(pw[(gr + 8) * 68 + s0 + gc]);
            uint32_t a2 = __float_as_uint(pw[gr * 68 + s0 + gc + 4]);
            uint32_t a3 = __float_as_uint(pw[(gr + 8) * 68 + s0 + gc + 4]);
#pragma unroll
            for (int ht = 0; ht < 16; ht++) {
                uint32_t b0 = __float_as_uint(sV[(s0 + gc) * 136 + ht * 8 + gr]);
                uint32_t b1 = __float_as_uint(sV[(s0 + gc + 4) * 136 + ht * 8 + gr]);
                mma8(o[ht], a0, a1, a2, a3, b0, b1);
            }
        }
    }

    // Epilogue: normalize and store
    const float i0 = 1.f / lrow[0];
    const float i1 = 1.f / lrow[1];
    const int r0 = qi * 128 + m0 + gr;
    float* og = out + (size_t)b * Tn * Hn;
#pragma unroll
    for (int ht = 0; ht < 16; ht++) {
        int col = ht * 8 + 2 * gc;
        *(float2*)(og + (size_t)r0 * Hn + col) =
            make_float2(o[ht][0] * i0, o[ht][1] * i0);
        *(float2*)(og + (size_t)(r0 + 8) * Hn + col) =
            make_float2(o[ht][2] * i1, o[ht][3] * i1);
    }
}

extern "C" void kernel_launch(void* const* d_in, const int* in_sizes, int n_in,
                              void* d_out, int out_size) {
    const float* x = (const float*)d_in[0];
    const float* Wq = (const float*)d_in[1];
    const float* Wk = (const float*)d_in[2];
    const float* Wv = (const float*)d_in[3];

    cudaFuncSetAttribute(proj_kernel, cudaFuncAttributeMaxDynamicSharedMemorySize, PROJ_SMEM);
    cudaFuncSetAttribute(attn_kernel, cudaFuncAttributeMaxDynamicSharedMemorySize, ATTN_SMEM);

    // M-tiles: 32768/128 = 256; y: {Wq,Wk,Wv} x {col half}
    proj_kernel<<<dim3(256, 6), 256, PROJ_SMEM>>>(x, Wq, Wk, Wv);
    // x: 16 q-tiles (reversed inside kernel for load balance), y: 16 batches
    attn_kernel<<<dim3(16, 16), 256, ATTN_SMEM>>>((float*)d_out);
}